// round 5
// baseline (speedup 1.0000x reference)
#include <cuda_runtime.h>
#include <cstdint>

// TinyGRU: B=4096, S=2048, I=3, H=4, O=2
// outputs [B,S,O] then h_final [B,H] concatenated in d_out (float32).
//
// One thread per batch row. 128 warps total -> ~1 warp/SM; per-step cost is
// bounded by MUFU throughput (24 MUFU/step * rt 8 = ~192 cyc/step/warp).

#define GRU_B 4096
#define GRU_S 2048
#define GRU_I 3
#define GRU_H 4
#define GRU_O 2

__device__ __forceinline__ float fast_ex2(float x) {
    float y;
    asm("ex2.approx.ftz.f32 %0, %1;" : "=f"(y) : "f"(x));
    return y;
}
__device__ __forceinline__ float fast_rcp(float x) {
    float y;
    asm("rcp.approx.ftz.f32 %0, %1;" : "=f"(y) : "f"(x));
    return y;
}
// sigmoid(x) = 1 / (1 + 2^(-x*log2e))
__device__ __forceinline__ float sigmoid_f(float x) {
    return fast_rcp(1.0f + fast_ex2(-1.4426950408889634f * x));
}
// tanh(x) = 1 - 2 / (2^(2x*log2e) + 1)
__device__ __forceinline__ float tanh_f(float x) {
    return fmaf(-2.0f, fast_rcp(1.0f + fast_ex2(2.8853900817779268f * x)), 1.0f);
}

__global__ void __launch_bounds__(32, 1)
tinygru_kernel(const float* __restrict__ inp,     // [B,S,I]
               const float* __restrict__ W_ih,    // [12,3]
               const float* __restrict__ W_hh,    // [12,4]
               const float* __restrict__ b_ih,    // [12]
               const float* __restrict__ b_hh,    // [12]
               const float* __restrict__ W_ro,    // [2,4]
               const float* __restrict__ b_ro,    // [2]
               const float* __restrict__ h0,      // [1,4]
               float* __restrict__ out)           // [B*S*O + B*H]
{
    const int b = blockIdx.x * 32 + threadIdx.x;

    // ---- load all weights into registers (broadcast loads) ----
    float wih[12][3], whh[12][4], bi[12], bhn[4];
    #pragma unroll
    for (int g = 0; g < 12; ++g) {
        #pragma unroll
        for (int i = 0; i < 3; ++i) wih[g][i] = W_ih[g * 3 + i];
        #pragma unroll
        for (int k = 0; k < 4; ++k) whh[g][k] = W_hh[g * 4 + k];
        bi[g] = b_ih[g];
    }
    // fold b_hh into the input-side bias for r,z gates (they only appear summed);
    // n gate needs hn = W_hh_n h + b_hh_n kept separate (multiplied by r).
    #pragma unroll
    for (int g = 0; g < 8; ++g) bi[g] += b_hh[g];
    #pragma unroll
    for (int j = 0; j < 4; ++j) bhn[j] = b_hh[8 + j];

    float wro[2][4], bro[2];
    #pragma unroll
    for (int o = 0; o < 2; ++o) {
        #pragma unroll
        for (int k = 0; k < 4; ++k) wro[o][k] = W_ro[o * 4 + k];
        bro[o] = b_ro[o];
    }

    float h[4];
    #pragma unroll
    for (int j = 0; j < 4; ++j) h[j] = h0[j];

    // ---- streaming pointers (all 16B aligned: S*I=6144, S*O=4096 floats/row) ----
    const float4* __restrict__ xin =
        (const float4*)(inp + (size_t)b * GRU_S * GRU_I);
    float4* __restrict__ yo = (float4*)(out + (size_t)b * GRU_S * GRU_O);

    const int NCHUNK = GRU_S / 4;  // 4 steps per chunk = 12 input floats = 3 float4

    float4 A0 = __ldg(xin + 0);
    float4 A1 = __ldg(xin + 1);
    float4 A2 = __ldg(xin + 2);

    for (int c = 0; c < NCHUNK; ++c) {
        // prefetch next chunk (clamped; overlaps with ~770 cycles of compute)
        const int nc = min(c + 1, NCHUNK - 1);
        float4 B0 = __ldg(xin + 3 * nc + 0);
        float4 B1 = __ldg(xin + 3 * nc + 1);
        float4 B2 = __ldg(xin + 3 * nc + 2);

        const float xs[12] = {A0.x, A0.y, A0.z, A0.w,
                              A1.x, A1.y, A1.z, A1.w,
                              A2.x, A2.y, A2.z, A2.w};
        float os[8];

        #pragma unroll
        for (int t = 0; t < 4; ++t) {
            const float x0 = xs[3 * t + 0];
            const float x1 = xs[3 * t + 1];
            const float x2 = xs[3 * t + 2];

            // input-side gates: xg[g] = bi[g] + W_ih[g,:] . x
            float xg[12];
            #pragma unroll
            for (int g = 0; g < 12; ++g)
                xg[g] = fmaf(wih[g][2], x2,
                        fmaf(wih[g][1], x1,
                        fmaf(wih[g][0], x0, bi[g])));

            // hidden-side: pr/pz are full pre-activations; hn kept separate
            float r[4], z[4], n[4];
            #pragma unroll
            for (int j = 0; j < 4; ++j) {
                float pr = xg[j];
                float pz = xg[4 + j];
                float hn = bhn[j];
                #pragma unroll
                for (int k = 0; k < 4; ++k) {
                    pr = fmaf(whh[j][k],     h[k], pr);
                    pz = fmaf(whh[4 + j][k], h[k], pz);
                    hn = fmaf(whh[8 + j][k], h[k], hn);
                }
                r[j] = sigmoid_f(pr);
                z[j] = sigmoid_f(pz);
                n[j] = tanh_f(fmaf(r[j], hn, xg[8 + j]));
            }
            // h = (1-z)*n + z*h = n + z*(h - n)
            #pragma unroll
            for (int j = 0; j < 4; ++j)
                h[j] = fmaf(z[j], h[j] - n[j], n[j]);

            // readout on the updated state
            #pragma unroll
            for (int o = 0; o < 2; ++o) {
                float acc = bro[o];
                #pragma unroll
                for (int k = 0; k < 4; ++k) acc = fmaf(wro[o][k], h[k], acc);
                os[2 * t + o] = acc;
            }
        }

        yo[2 * c + 0] = make_float4(os[0], os[1], os[2], os[3]);
        yo[2 * c + 1] = make_float4(os[4], os[5], os[6], os[7]);

        A0 = B0; A1 = B1; A2 = B2;
    }

    // ---- h_final at out + B*S*O, [B,H], 16B aligned per batch ----
    float4* __restrict__ hf =
        (float4*)(out + (size_t)GRU_B * GRU_S * GRU_O);
    hf[b] = make_float4(h[0], h[1], h[2], h[3]);
}

extern "C" void kernel_launch(void* const* d_in, const int* in_sizes, int n_in,
                              void* d_out, int out_size) {
    const float* inp  = (const float*)d_in[0];
    const float* W_ih = (const float*)d_in[1];
    const float* W_hh = (const float*)d_in[2];
    const float* b_ih = (const float*)d_in[3];
    const float* b_hh = (const float*)d_in[4];
    const float* W_ro = (const float*)d_in[5];
    const float* b_ro = (const float*)d_in[6];
    const float* h0   = (const float*)d_in[7];
    float* out = (float*)d_out;

    tinygru_kernel<<<GRU_B / 32, 32>>>(inp, W_ih, W_hh, b_ih, b_hh,
                                       W_ro, b_ro, h0, out);
}

// round 6
// speedup vs baseline: 1.1686x; 1.1686x over previous
#include <cuda_runtime.h>
#include <cstdint>

// TinyGRU: B=4096, S=2048, I=3, H=4, O=2
// outputs [B,S,O] then h_final [B,H] concatenated in d_out (float32).
//
// One thread per batch. 128 warps on 148 SMs -> fixed 1 warp/SM; wall time is
// per-warp instruction throughput. This version:
//   * fma.rn.f32x2 (FFMA2) packs the 12 gate dot-products into 6 paired chains
//     (ptxas never emits FFMA2 on its own)
//   * r,z gates via MUFU.TANH sigmoid (x0.5 folded into weights at setup);
//     n gate keeps the accurate ex2/rcp tanh (its error enters h unattenuated)

#define GRU_B 4096
#define GRU_S 2048
#define GRU_I 3
#define GRU_H 4
#define GRU_O 2

typedef unsigned long long ull;

__device__ __forceinline__ ull pack2(float lo, float hi) {
    ull d; asm("mov.b64 %0, {%1, %2};" : "=l"(d) : "f"(lo), "f"(hi)); return d;
}
__device__ __forceinline__ void unpack2(float& lo, float& hi, ull s) {
    asm("mov.b64 {%0, %1}, %2;" : "=f"(lo), "=f"(hi) : "l"(s));
}
__device__ __forceinline__ ull fma2(ull a, ull b, ull c) {
    ull d; asm("fma.rn.f32x2 %0, %1, %2, %3;" : "=l"(d) : "l"(a), "l"(b), "l"(c));
    return d;
}
__device__ __forceinline__ float tanh_fast(float x) {
    float y; asm("tanh.approx.f32 %0, %1;" : "=f"(y) : "f"(x)); return y;
}
__device__ __forceinline__ float fast_ex2(float x) {
    float y; asm("ex2.approx.ftz.f32 %0, %1;" : "=f"(y) : "f"(x)); return y;
}
__device__ __forceinline__ float fast_rcp(float x) {
    float y; asm("rcp.approx.ftz.f32 %0, %1;" : "=f"(y) : "f"(x)); return y;
}
// accurate tanh(x) = 1 - 2/(2^(2x*log2e) + 1)
__device__ __forceinline__ float tanh_acc(float x) {
    return fmaf(-2.0f, fast_rcp(1.0f + fast_ex2(2.8853900817779268f * x)), 1.0f);
}

__global__ void __launch_bounds__(32, 1)
tinygru_kernel(const float* __restrict__ inp,     // [B,S,I]
               const float* __restrict__ W_ih,    // [12,3]
               const float* __restrict__ W_hh,    // [12,4]
               const float* __restrict__ b_ih,    // [12]
               const float* __restrict__ b_hh,    // [12]
               const float* __restrict__ W_ro,    // [2,4]
               const float* __restrict__ b_ro,    // [2]
               const float* __restrict__ h0,      // [1,4]
               float* __restrict__ out)           // [B*S*O + B*H]
{
    const int b = blockIdx.x * 32 + threadIdx.x;

    // ---- scalar weight load (broadcast) ----
    float wih[12][3], whh[12][4], bi[12], bhn[4];
    #pragma unroll
    for (int g = 0; g < 12; ++g) {
        #pragma unroll
        for (int i = 0; i < 3; ++i) wih[g][i] = W_ih[g * 3 + i];
        #pragma unroll
        for (int k = 0; k < 4; ++k) whh[g][k] = W_hh[g * 4 + k];
    }
    // r,z gates (0..7): combine biases and fold sigmoid's x0.5 into everything.
    #pragma unroll
    for (int g = 0; g < 8; ++g) {
        bi[g] = 0.5f * (b_ih[g] + b_hh[g]);
        #pragma unroll
        for (int i = 0; i < 3; ++i) wih[g][i] *= 0.5f;
        #pragma unroll
        for (int k = 0; k < 4; ++k) whh[g][k] *= 0.5f;
    }
    // n gate: x-side and h-side biases kept separate (hn multiplied by r).
    #pragma unroll
    for (int j = 0; j < 4; ++j) { bi[8 + j] = b_ih[8 + j]; bhn[j] = b_hh[8 + j]; }

    // ---- pack weights: pair p covers gates (2p, 2p+1), p = 0..5 ----
    ull wx2[6][3], wh2[6][4];
    #pragma unroll
    for (int p = 0; p < 6; ++p) {
        #pragma unroll
        for (int i = 0; i < 3; ++i) wx2[p][i] = pack2(wih[2 * p][i], wih[2 * p + 1][i]);
        #pragma unroll
        for (int k = 0; k < 4; ++k) wh2[p][k] = pack2(whh[2 * p][k], whh[2 * p + 1][k]);
    }
    ull brz2[4];
    #pragma unroll
    for (int p = 0; p < 4; ++p) brz2[p] = pack2(bi[2 * p], bi[2 * p + 1]);
    const ull bxn2_0 = pack2(bi[8], bi[9]),  bxn2_1 = pack2(bi[10], bi[11]);
    const ull bhn2_0 = pack2(bhn[0], bhn[1]), bhn2_1 = pack2(bhn[2], bhn[3]);

    ull wro2[4];
    #pragma unroll
    for (int k = 0; k < 4; ++k) wro2[k] = pack2(W_ro[k], W_ro[4 + k]);
    const ull bro2 = pack2(b_ro[0], b_ro[1]);

    float h[4];
    ull hh[4];
    #pragma unroll
    for (int j = 0; j < 4; ++j) { h[j] = h0[j]; hh[j] = pack2(h[j], h[j]); }

    // ---- streaming pointers (16B aligned: S*I=6144, S*O=4096 floats/row) ----
    const float4* __restrict__ xin = (const float4*)(inp + (size_t)b * GRU_S * GRU_I);
    float4* __restrict__ yo = (float4*)(out + (size_t)b * GRU_S * GRU_O);

    const int NCHUNK = GRU_S / 4;  // 4 steps = 12 input floats = 3 float4

    float4 A0 = __ldg(xin + 0);
    float4 A1 = __ldg(xin + 1);
    float4 A2 = __ldg(xin + 2);

    for (int c = 0; c < NCHUNK; ++c) {
        const int nc = min(c + 1, NCHUNK - 1);
        float4 B0 = __ldg(xin + 3 * nc + 0);
        float4 B1 = __ldg(xin + 3 * nc + 1);
        float4 B2 = __ldg(xin + 3 * nc + 2);

        const float xs[12] = {A0.x, A0.y, A0.z, A0.w,
                              A1.x, A1.y, A1.z, A1.w,
                              A2.x, A2.y, A2.z, A2.w};
        float os[8];

        #pragma unroll
        for (int t = 0; t < 4; ++t) {
            const ull xx0 = pack2(xs[3 * t + 0], xs[3 * t + 0]);
            const ull xx1 = pack2(xs[3 * t + 1], xs[3 * t + 1]);
            const ull xx2 = pack2(xs[3 * t + 2], xs[3 * t + 2]);

            // r,z pre-activations (already x0.5): pairs p=0..3
            ull a[4];
            #pragma unroll
            for (int p = 0; p < 4; ++p) {
                ull acc = brz2[p];
                acc = fma2(wx2[p][0], xx0, acc);
                acc = fma2(wx2[p][1], xx1, acc);
                acc = fma2(wx2[p][2], xx2, acc);
                #pragma unroll
                for (int k = 0; k < 4; ++k) acc = fma2(wh2[p][k], hh[k], acc);
                a[p] = acc;
            }
            // n gate x-side (pairs p=4,5)
            ull xn0 = bxn2_0, xn1 = bxn2_1;
            xn0 = fma2(wx2[4][0], xx0, xn0); xn1 = fma2(wx2[5][0], xx0, xn1);
            xn0 = fma2(wx2[4][1], xx1, xn0); xn1 = fma2(wx2[5][1], xx1, xn1);
            xn0 = fma2(wx2[4][2], xx2, xn0); xn1 = fma2(wx2[5][2], xx2, xn1);
            // n gate h-side
            ull hn0 = bhn2_0, hn1 = bhn2_1;
            #pragma unroll
            for (int k = 0; k < 4; ++k) {
                hn0 = fma2(wh2[4][k], hh[k], hn0);
                hn1 = fma2(wh2[5][k], hh[k], hn1);
            }

            // activations
            float pr[4], pz[4], xnv[4], hnv[4];
            unpack2(pr[0], pr[1], a[0]); unpack2(pr[2], pr[3], a[1]);
            unpack2(pz[0], pz[1], a[2]); unpack2(pz[2], pz[3], a[3]);
            unpack2(xnv[0], xnv[1], xn0); unpack2(xnv[2], xnv[3], xn1);
            unpack2(hnv[0], hnv[1], hn0); unpack2(hnv[2], hnv[3], hn1);

            #pragma unroll
            for (int j = 0; j < 4; ++j) {
                const float r = fmaf(0.5f, tanh_fast(pr[j]), 0.5f);
                const float z = fmaf(0.5f, tanh_fast(pz[j]), 0.5f);
                const float n = tanh_acc(fmaf(r, hnv[j], xnv[j]));
                h[j] = fmaf(z, h[j] - n, n);
            }
            #pragma unroll
            for (int j = 0; j < 4; ++j) hh[j] = pack2(h[j], h[j]);

            // readout (packed over the two outputs)
            ull o2 = bro2;
            #pragma unroll
            for (int k = 0; k < 4; ++k) o2 = fma2(wro2[k], hh[k], o2);
            unpack2(os[2 * t + 0], os[2 * t + 1], o2);
        }

        yo[2 * c + 0] = make_float4(os[0], os[1], os[2], os[3]);
        yo[2 * c + 1] = make_float4(os[4], os[5], os[6], os[7]);

        A0 = B0; A1 = B1; A2 = B2;
    }

    // ---- h_final at out + B*S*O ----
    float4* __restrict__ hf = (float4*)(out + (size_t)GRU_B * GRU_S * GRU_O);
    hf[b] = make_float4(h[0], h[1], h[2], h[3]);
}

extern "C" void kernel_launch(void* const* d_in, const int* in_sizes, int n_in,
                              void* d_out, int out_size) {
    const float* inp  = (const float*)d_in[0];
    const float* W_ih = (const float*)d_in[1];
    const float* W_hh = (const float*)d_in[2];
    const float* b_ih = (const float*)d_in[3];
    const float* b_hh = (const float*)d_in[4];
    const float* W_ro = (const float*)d_in[5];
    const float* b_ro = (const float*)d_in[6];
    const float* h0   = (const float*)d_in[7];
    float* out = (float*)d_out;

    tinygru_kernel<<<GRU_B / 32, 32>>>(inp, W_ih, W_hh, b_ih, b_hh,
                                       W_ro, b_ro, h0, out);
}

// round 7
// speedup vs baseline: 1.8054x; 1.5450x over previous
#include <cuda_runtime.h>
#include <cstdint>

// TinyGRU: B=4096, S=2048, I=3, H=4, O=2
// outputs [B,S,O] then h_final [B,H] concatenated in d_out (float32).
//
// Lane-parallel: 4 lanes per batch; lane j owns h[j] and gates (r_j, z_j, n_j).
// 16384 threads = 512 warps -> 128 blocks x 128 threads = 4 warps/SM, one per
// SMSP (vs 1 warp/SM before). h exchanged via 4 independent shfl.idx per step.
// r,z packed into one fma.rn.f32x2 chain; all activations via MUFU.TANH
// (sigmoid(x) = 0.5*tanh(x/2)+0.5 with the 0.5 folded into weights).

#define GRU_B 4096
#define GRU_S 2048
#define GRU_I 3
#define GRU_H 4
#define GRU_O 2

typedef unsigned long long ull;

__device__ __forceinline__ ull pack2(float lo, float hi) {
    ull d; asm("mov.b64 %0, {%1, %2};" : "=l"(d) : "f"(lo), "f"(hi)); return d;
}
__device__ __forceinline__ void unpack2(float& lo, float& hi, ull s) {
    asm("mov.b64 {%0, %1}, %2;" : "=f"(lo), "=f"(hi) : "l"(s));
}
__device__ __forceinline__ ull fma2(ull a, ull b, ull c) {
    ull d; asm("fma.rn.f32x2 %0, %1, %2, %3;" : "=l"(d) : "l"(a), "l"(b), "l"(c));
    return d;
}
__device__ __forceinline__ float tanh_fast(float x) {
    float y; asm("tanh.approx.f32 %0, %1;" : "=f"(y) : "f"(x)); return y;
}

__global__ void __launch_bounds__(128, 1)
tinygru_kernel(const float* __restrict__ inp,     // [B,S,I]
               const float* __restrict__ W_ih,    // [12,3]
               const float* __restrict__ W_hh,    // [12,4]
               const float* __restrict__ b_ih,    // [12]
               const float* __restrict__ b_hh,    // [12]
               const float* __restrict__ W_ro,    // [2,4]
               const float* __restrict__ b_ro,    // [2]
               const float* __restrict__ h0,      // [1,4]
               float* __restrict__ out)           // [B*S*O + B*H]
{
    const int t  = blockIdx.x * 128 + threadIdx.x;
    const int b  = t >> 2;                 // batch row
    const int j  = t & 3;                  // owned h component / gate row
    const int qbase = (threadIdx.x & 31) & ~3;  // lane of j=0 in my quad

    // ---- per-lane weights: gate rows j (r), 4+j (z), 8+j (n) ----
    const int jr = j, jz = 4 + j, jn = 8 + j;

    ull wxrz[3], whrz[4];
    #pragma unroll
    for (int i = 0; i < 3; ++i)
        wxrz[i] = pack2(0.5f * W_ih[jr * 3 + i], 0.5f * W_ih[jz * 3 + i]);
    #pragma unroll
    for (int k = 0; k < 4; ++k)
        whrz[k] = pack2(0.5f * W_hh[jr * 4 + k], 0.5f * W_hh[jz * 4 + k]);
    const ull brz = pack2(0.5f * (b_ih[jr] + b_hh[jr]),
                          0.5f * (b_ih[jz] + b_hh[jz]));

    float wxn[3], whn[4];
    #pragma unroll
    for (int i = 0; i < 3; ++i) wxn[i] = W_ih[jn * 3 + i];
    #pragma unroll
    for (int k = 0; k < 4; ++k) whn[k] = W_hh[jn * 4 + k];
    const float bxn = b_ih[jn], bhn = b_hh[jn];

    ull wro2[4];
    #pragma unroll
    for (int k = 0; k < 4; ++k) wro2[k] = pack2(W_ro[k], W_ro[4 + k]);
    const ull bro2 = pack2(b_ro[0], b_ro[1]);

    // ---- state ----
    float hfull[4];
    #pragma unroll
    for (int k = 0; k < 4; ++k) hfull[k] = h0[k];
    float hj = hfull[j];
    ull hh2[4];
    #pragma unroll
    for (int k = 0; k < 4; ++k) hh2[k] = pack2(hfull[k], hfull[k]);

    // ---- streaming pointers (all lanes of a quad read the same x) ----
    const float4* __restrict__ xin = (const float4*)(inp + (size_t)b * GRU_S * GRU_I);
    float2* __restrict__ yo = (float2*)(out + (size_t)b * GRU_S * GRU_O);

    const int NCHUNK = GRU_S / 4;   // 4 steps = 12 floats = 3 float4

    float4 A0 = __ldg(xin + 0);
    float4 A1 = __ldg(xin + 1);
    float4 A2 = __ldg(xin + 2);

    for (int c = 0; c < NCHUNK; ++c) {
        const int nc = min(c + 1, NCHUNK - 1);
        float4 B0 = __ldg(xin + 3 * nc + 0);
        float4 B1 = __ldg(xin + 3 * nc + 1);
        float4 B2 = __ldg(xin + 3 * nc + 2);

        const float xs[12] = {A0.x, A0.y, A0.z, A0.w,
                              A1.x, A1.y, A1.z, A1.w,
                              A2.x, A2.y, A2.z, A2.w};

        // x-side gate projections for all 4 steps (independent of h;
        // fills latency-stall slots of the recurrence)
        ull  xrz[4];
        float xnv[4];
        #pragma unroll
        for (int q = 0; q < 4; ++q) {
            const float x0 = xs[3 * q + 0], x1 = xs[3 * q + 1], x2 = xs[3 * q + 2];
            ull a = brz;
            a = fma2(wxrz[0], pack2(x0, x0), a);
            a = fma2(wxrz[1], pack2(x1, x1), a);
            a = fma2(wxrz[2], pack2(x2, x2), a);
            xrz[q] = a;
            xnv[q] = fmaf(wxn[2], x2, fmaf(wxn[1], x1, fmaf(wxn[0], x0, bxn)));
        }

        #pragma unroll
        for (int q = 0; q < 4; ++q) {
            // r,z pre-activations (packed, already scaled by 0.5)
            ull prz = xrz[q];
            #pragma unroll
            for (int k = 0; k < 4; ++k) prz = fma2(whrz[k], hh2[k], prz);

            // n-gate hidden side (runs in parallel with the packed chain)
            float hn = bhn;
            #pragma unroll
            for (int k = 0; k < 4; ++k) hn = fmaf(whn[k], hfull[k], hn);

            float pr, pz; unpack2(pr, pz, prz);
            const float tr = tanh_fast(pr);
            const float tz = tanh_fast(pz);

            // n = tanh(xn + (0.5*tr + 0.5) * hn)
            const float hnh  = 0.5f * hn;
            const float npre = fmaf(tr, hnh, hnh + xnv[q]);
            const float n    = tanh_fast(npre);

            // h' = 0.5*(n + h) + 0.5*tz*(h - n)
            const float tzh = 0.5f * tz;              // overlaps tanh(npre)
            const float s   = 0.5f * (n + hj);
            hj = fmaf(tzh, hj - n, s);

            // exchange new h across the quad (4 independent shfl.idx)
            hfull[0] = __shfl_sync(0xffffffffu, hj, qbase + 0);
            hfull[1] = __shfl_sync(0xffffffffu, hj, qbase + 1);
            hfull[2] = __shfl_sync(0xffffffffu, hj, qbase + 2);
            hfull[3] = __shfl_sync(0xffffffffu, hj, qbase + 3);
            #pragma unroll
            for (int k = 0; k < 4; ++k) hh2[k] = pack2(hfull[k], hfull[k]);

            // readout on the updated state (packed over the 2 outputs);
            // only lane j==0 of each quad stores
            ull o2 = bro2;
            #pragma unroll
            for (int k = 0; k < 4; ++k) o2 = fma2(wro2[k], hh2[k], o2);
            if (j == 0) {
                float o0, o1; unpack2(o0, o1, o2);
                yo[4 * c + q] = make_float2(o0, o1);
            }
        }

        A0 = B0; A1 = B1; A2 = B2;
    }

    // ---- h_final: lane j writes its component (coalesced float per lane) ----
    out[(size_t)GRU_B * GRU_S * GRU_O + (size_t)b * GRU_H + j] = hj;
}

extern "C" void kernel_launch(void* const* d_in, const int* in_sizes, int n_in,
                              void* d_out, int out_size) {
    const float* inp  = (const float*)d_in[0];
    const float* W_ih = (const float*)d_in[1];
    const float* W_hh = (const float*)d_in[2];
    const float* b_ih = (const float*)d_in[3];
    const float* b_hh = (const float*)d_in[4];
    const float* W_ro = (const float*)d_in[5];
    const float* b_ro = (const float*)d_in[6];
    const float* h0   = (const float*)d_in[7];
    float* out = (float*)d_out;

    tinygru_kernel<<<(GRU_B * GRU_H) / 128, 128>>>(inp, W_ih, W_hh, b_ih, b_hh,
                                                   W_ro, b_ro, h0, out);
}